// round 5
// baseline (speedup 1.0000x reference)
#include <cuda_runtime.h>
#include <cuda_bf16.h>

// TenHotEncodeLayer: out[n, t, x[n,t,f]] = 1.0 for f in [0,10); all else 0.
// x: [32, 512, 10] int32, out: [32, 512, 5000] float32.
//
// Strategy v5: one WARP per row. grid = 2048 CTAs x 8 warps = 16384 warps
// = 16384 rows. Each warp:
//   - lanes 0-9 prefetch the row's 10 indices (hidden under the fill)
//   - streams 1250 float4 zeros: 39 unrolled STG.128 + 2-lane tail,
//     perfectly coalesced 512B per instruction, evict-first (__stcs)
//   - __syncwarp() only (no block barrier, warps retire independently)
//   - lanes 0-9 overwrite indexed positions with 1.0 (lines L2-hot)

#define NUM_TOKENS 5000
#define ROW_F4 (NUM_TOKENS / 4)   // 1250
#define NUM_F 10
#define TPB 256                   // 8 warps per CTA
#define WARPS_PER_CTA (TPB / 32)
#define FULL_ITERS (ROW_F4 / 32)  // 39
#define TAIL_LANES (ROW_F4 - FULL_ITERS * 32)  // 2

__global__ __launch_bounds__(TPB) void tenhot_kernel(
    const int* __restrict__ x, float4* __restrict__ out)
{
    const int warp = threadIdx.x >> 5;
    const int lane = threadIdx.x & 31;
    const int row  = blockIdx.x * WARPS_PER_CTA + warp;

    // Prefetch this lane's scatter index early (hidden under the fill).
    int c = 0;
    if (lane < NUM_F) c = __ldg(&x[row * NUM_F + lane]);

    float4* o = out + (size_t)row * ROW_F4;
    const float4 z = make_float4(0.f, 0.f, 0.f, 0.f);

    // 1250 = 39*32 + 2: fully unrolled streaming fill, deep store MLP.
#pragma unroll
    for (int k = 0; k < FULL_ITERS; k++)
        __stcs(&o[lane + 32 * k], z);
    if (lane < TAIL_LANES)
        __stcs(&o[lane + 32 * FULL_ITERS], z);

    __syncwarp();

    if (lane < NUM_F)
        reinterpret_cast<float*>(o)[c] = 1.0f;
}

extern "C" void kernel_launch(void* const* d_in, const int* in_sizes, int n_in,
                              void* d_out, int out_size)
{
    const int* x = (const int*)d_in[0];
    float4* out = (float4*)d_out;
    const int rows = in_sizes[0] / NUM_F;            // 16384
    tenhot_kernel<<<rows / WARPS_PER_CTA, TPB>>>(x, out);
}

// round 6
// speedup vs baseline: 1.0802x; 1.0802x over previous
#include <cuda_runtime.h>
#include <cuda_bf16.h>

// TenHotEncodeLayer: out[n, t, x[n,t,f]] = 1.0 for f in [0,10); all else 0.
// x: [32, 512, 10] int32, out: [32, 512, 5000] float32 (flat 81,920,000 elems).
//
// Strategy v6: ALIGNED flat-range partitioning. A row (20000 B) is not
// 128B-aligned (20000 % 128 = 32), so row-per-CTA fills straddle L2 lines
// (5 lines per 512B warp store instead of 4) and share boundary lines
// between CTAs. Instead each CTA owns an aligned 10240 B range:
//   - 8000 CTAs x 2560 float4; 256 threads x 10 unrolled STG.128, no tail,
//     every warp store = exactly 4 full 128B lines, every line one owner.
//   - The range intersects <= 3 rows; threads 0..(nrows*10-1) prefetch the
//     indices of those rows before the fill, and after a block barrier
//     patch 1.0f at in-range flat positions (lines still L2-hot).

#define NUM_TOKENS 5000
#define NUM_F 10
#define TPB 256
#define CTA_F4 2560                    // 10240 B = 80 * 128B lines
#define CTA_ELEMS (CTA_F4 * 4)         // 10240 floats
#define ITERS (CTA_F4 / TPB)           // 10, exact
#define GRID 8000                      // 20,480,000 f4 / 2560

__global__ __launch_bounds__(TPB) void tenhot_kernel(
    const int* __restrict__ x, float4* __restrict__ out)
{
    const int blk = blockIdx.x;
    const int tid = threadIdx.x;

    // Flat element range owned by this CTA: [s, s + CTA_ELEMS)
    const long long s = (long long)blk * CTA_ELEMS;
    const int row_lo = (int)(s / NUM_TOKENS);
    const int row_hi = (int)((s + CTA_ELEMS - 1) / NUM_TOKENS);
    const int npatch = (row_hi - row_lo + 1) * NUM_F;   // <= 30

    // Prefetch scatter candidates before the fill (latency hidden).
    long long flat = -1;
    if (tid < npatch) {
        int r = row_lo + tid / NUM_F;
        int f = tid - (tid / NUM_F) * NUM_F;
        int c = __ldg(&x[r * NUM_F + f]);
        long long p = (long long)r * NUM_TOKENS + c;
        if (p >= s && p < s + CTA_ELEMS) flat = p;
    }

    // Aligned streaming fill: 10 x STG.128, each warp op = 4 full lines.
    float4* o = out + (size_t)blk * CTA_F4;
    const float4 z = make_float4(0.f, 0.f, 0.f, 0.f);
#pragma unroll
    for (int k = 0; k < ITERS; k++)
        __stcs(&o[tid + TPB * k], z);

    __syncthreads();

    if (flat >= 0)
        reinterpret_cast<float*>(out)[flat] = 1.0f;
}

extern "C" void kernel_launch(void* const* d_in, const int* in_sizes, int n_in,
                              void* d_out, int out_size)
{
    const int* x = (const int*)d_in[0];
    float4* out = (float4*)d_out;
    tenhot_kernel<<<GRID, TPB>>>(x, out);
}